// round 14
// baseline (speedup 1.0000x reference)
#include <cuda_runtime.h>
#include <cuda_bf16.h>

// ChamferDistance: B=4, C=3, N=M=8192, fp32 -> scalar.
// R14 = R2/R12 geometry + manual double-buffered LDS pipeline (R13 minus the
//       illegal max.f32x2 — packed max does not exist on sm_100; scalar FMNMX back).
// Engine: t = x.y - 0.5||y||^2 (packed fma.rn.f32x2 pairs); per-query scalar max;
//         t_full = max - hx <= 0 -> raw-bit atomicMin merge; fused last-block sum.

#define NPTS    8192
#define NBATCH  4
#define THREADS 128
#define QPT     4
#define QTILE   (THREADS * QPT)          // 512 queries per block
#define NQT     (NPTS / QTILE)           // 16
#define TCHUNK  512                      // targets per block
#define NTC     (NPTS / TCHUNK)          // 16
#define NJ      (TCHUNK / 4)             // 128 inner iterations
#define NBLOCKS (2 * NBATCH * NQT * NTC) // 2048
#define NKEYS   (2 * NBATCH * NPTS)      // 65536
#define NEG_INF (-3.402823466e38f)

__device__ unsigned g_key[NKEYS];   // raw bits of t_full (<=0), merged via umin
__device__ unsigned g_count;

typedef unsigned long long u64;

__device__ __forceinline__ u64 fma2(u64 a, u64 b, u64 c) {
    u64 d;
    asm("fma.rn.f32x2 %0, %1, %2, %3;" : "=l"(d) : "l"(a), "l"(b), "l"(c));
    return d;
}
__device__ __forceinline__ u64 pack2(float x) {
    u64 d;
    asm("mov.b64 %0, {%1, %1};" : "=l"(d) : "f"(x));
    return d;
}
__device__ __forceinline__ void unpack2(u64 v, float& lo, float& hi) {
    asm("mov.b64 {%0, %1}, %2;" : "=f"(lo), "=f"(hi) : "l"(v));
}
__device__ __forceinline__ void lds_v2u64(unsigned addr, u64& a, u64& b) {
    asm volatile("ld.shared.v2.u64 {%0, %1}, [%2];" : "=l"(a), "=l"(b) : "r"(addr));
}

__global__ void chamfer_init_kernel() {
    int i = blockIdx.x * blockDim.x + threadIdx.x;
    g_key[i] = 0xFFFFFFFFu;   // umin identity
    if (i == 0) g_count = 0u;
}

__global__ __launch_bounds__(THREADS)
void chamfer_main_kernel(const float* __restrict__ pred,
                         const float* __restrict__ targ,
                         float* __restrict__ out) {
    const int u   = blockIdx.x;
    const int tc  = u & (NTC - 1);
    const int qt  = (u >> 4) & (NQT - 1);
    const int b   = (u >> 8) & (NBATCH - 1);
    const int dir = u >> 10;

    const float* __restrict__ X = (dir ? targ : pred) + (size_t)b * 3 * NPTS;  // queries
    const float* __restrict__ Y = (dir ? pred : targ) + (size_t)b * 3 * NPTS;  // targets

    __shared__ float s_y0[TCHUNK], s_y1[TCHUNK], s_y2[TCHUNK], s_nh[TCHUNK];
    __shared__ float wsum[THREADS / 32];
    __shared__ unsigned s_flag;

    const int tid = threadIdx.x;

    // ---- stage target chunk SoA: y0, y1, y2, nh = -0.5*||y||^2 ----
    const int tbase = tc * TCHUNK;
    #pragma unroll
    for (int i = tid; i < TCHUNK; i += THREADS) {
        float y0 = Y[tbase + i];
        float y1 = Y[NPTS + tbase + i];
        float y2 = Y[2 * NPTS + tbase + i];
        s_y0[i] = y0;
        s_y1[i] = y1;
        s_y2[i] = y2;
        s_nh[i] = -0.5f * (y0 * y0 + y1 * y1 + y2 * y2);
    }

    // ---- QPT queries per thread: packed broadcast registers ----
    const int qbase = qt * QTILE;
    u64 xp0[QPT], xp1[QPT], xp2[QPT];
    float hx[QPT];
    #pragma unroll
    for (int q = 0; q < QPT; q++) {
        int n = qbase + q * THREADS + tid;
        float x0 = X[n];
        float x1 = X[NPTS + n];
        float x2 = X[2 * NPTS + n];
        xp0[q] = pack2(x0);
        xp1[q] = pack2(x1);
        xp2[q] = pack2(x2);
        hx[q] = 0.5f * (x0 * x0 + x1 * x1 + x2 * x2);
    }
    __syncthreads();

    const unsigned a0 = (unsigned)__cvta_generic_to_shared(s_y0);
    const unsigned a1 = (unsigned)__cvta_generic_to_shared(s_y1);
    const unsigned a2 = (unsigned)__cvta_generic_to_shared(s_y2);
    const unsigned ah = (unsigned)__cvta_generic_to_shared(s_nh);

    float m0[QPT], m1[QPT];
    #pragma unroll
    for (int q = 0; q < QPT; q++) { m0[q] = NEG_INF; m1[q] = NEG_INF; }

    // ---- double-buffered main loop: LDS for j+1 issued before compute of j ----
    u64 A0[2], A1[2], B0[2], B1[2], C0[2], C1[2], H0[2], H1[2];
    lds_v2u64(a0, A0[0], A1[0]);
    lds_v2u64(a1, B0[0], B1[0]);
    lds_v2u64(a2, C0[0], C1[0]);
    lds_v2u64(ah, H0[0], H1[0]);

    #pragma unroll 2
    for (int j = 0; j < NJ - 1; j++) {
        const int cur = j & 1;
        const int nxt = cur ^ 1;
        const unsigned off = (unsigned)(j + 1) * 16;
        lds_v2u64(a0 + off, A0[nxt], A1[nxt]);
        lds_v2u64(a1 + off, B0[nxt], B1[nxt]);
        lds_v2u64(a2 + off, C0[nxt], C1[nxt]);
        lds_v2u64(ah + off, H0[nxt], H1[nxt]);

        #pragma unroll
        for (int q = 0; q < QPT; q++) {
            u64 t0 = fma2(xp2[q], C0[cur], H0[cur]);
            u64 t1 = fma2(xp2[q], C1[cur], H1[cur]);
            t0 = fma2(xp1[q], B0[cur], t0);
            t1 = fma2(xp1[q], B1[cur], t1);
            t0 = fma2(xp0[q], A0[cur], t0);
            t1 = fma2(xp0[q], A1[cur], t1);
            float l0, h0, l1, h1;
            unpack2(t0, l0, h0);
            unpack2(t1, l1, h1);
            m0[q] = fmaxf(m0[q], l0);
            m1[q] = fmaxf(m1[q], h0);
            m0[q] = fmaxf(m0[q], l1);
            m1[q] = fmaxf(m1[q], h1);
        }
    }
    {   // final iteration (buffer index (NJ-1)&1 = 1)
        const int cur = (NJ - 1) & 1;
        #pragma unroll
        for (int q = 0; q < QPT; q++) {
            u64 t0 = fma2(xp2[q], C0[cur], H0[cur]);
            u64 t1 = fma2(xp2[q], C1[cur], H1[cur]);
            t0 = fma2(xp1[q], B0[cur], t0);
            t1 = fma2(xp1[q], B1[cur], t1);
            t0 = fma2(xp0[q], A0[cur], t0);
            t1 = fma2(xp0[q], A1[cur], t1);
            float l0, h0, l1, h1;
            unpack2(t0, l0, h0);
            unpack2(t1, l1, h1);
            m0[q] = fmaxf(m0[q], l0);
            m1[q] = fmaxf(m1[q], h0);
            m0[q] = fmaxf(m0[q], l1);
            m1[q] = fmaxf(m1[q], h1);
        }
    }

    // ---- epilogue: t_full = max - hx <= 0, merge via raw-bit umin ----
    const int key0 = (dir * NBATCH + b) * NPTS + qbase + tid;
    #pragma unroll
    for (int q = 0; q < QPT; q++) {
        float tf = fmaxf(m0[q], m1[q]) - hx[q];
        atomicMin(&g_key[key0 + q * THREADS], __float_as_uint(tf));
    }

    // ---- last block performs the final sum (fused reduce) ----
    __threadfence();
    if (tid == 0)
        s_flag = (atomicAdd(&g_count, 1u) == (unsigned)(NBLOCKS - 1)) ? 1u : 0u;
    __syncthreads();
    if (s_flag) {
        const uint4* kp = (const uint4*)g_key;
        float sa = 0.0f, sb = 0.0f, sc = 0.0f, sd = 0.0f;
        for (int i = tid; i < NKEYS / 4; i += THREADS) {
            uint4 v = __ldcg(&kp[i]);
            sa += __uint_as_float(v.x);
            sb += __uint_as_float(v.y);
            sc += __uint_as_float(v.z);
            sd += __uint_as_float(v.w);
        }
        float s = (sa + sb) + (sc + sd);
        #pragma unroll
        for (int off = 16; off > 0; off >>= 1)
            s += __shfl_xor_sync(0xffffffffu, s, off);
        if ((tid & 31) == 0) wsum[tid >> 5] = s;
        __syncthreads();
        if (tid == 0) {
            float t = 0.0f;
            #pragma unroll
            for (int i = 0; i < THREADS / 32; i++) t += wsum[i];
            // min dist per query = -2 * t_full; two means each over B*NPTS
            out[0] = t * (-2.0f / (float)(NBATCH * NPTS));
        }
    }
}

extern "C" void kernel_launch(void* const* d_in, const int* in_sizes, int n_in,
                              void* d_out, int out_size) {
    const float* pred = (const float*)d_in[0];
    const float* targ = (const float*)d_in[1];
    float* out = (float*)d_out;

    chamfer_init_kernel<<<NKEYS / 256, 256>>>();
    chamfer_main_kernel<<<NBLOCKS, THREADS>>>(pred, targ, out);
}

// round 15
// speedup vs baseline: 1.1700x; 1.1700x over previous
#include <cuda_runtime.h>
#include <cuda_bf16.h>

// ChamferDistance: B=4, C=3, N=M=8192, fp32.
// dist(n,m) = 2*hx - 2*(x.y - hy);  min_m dist = 2*hx - 2*max_m(x.y - hy)
// Packed fma.rn.f32x2 (Blackwell 2xFP32): 1.5 FFMA2 + 1 FMNMX per pair.
// Work split: (dir, batch, qtile 512, tchunk 512) = 2048 blocks, combined via float atomicMax.

#define NPTS     8192
#define NBATCH   4
#define THREADS  128
#define QPT      4            // queries per thread -> 512 queries per block
#define QTILE    (THREADS * QPT)
#define TCHUNK   512          // targets per block
#define NQT      (NPTS / QTILE)    // 16 query tiles
#define NTC      (NPTS / TCHUNK)   // 16 target chunks
#define NUNITS   (2 * NBATCH * NQT * NTC)   // 2048
#define NQUERY   (2 * NBATCH * NPTS)        // 65536

__device__ float g_mx[NQUERY];   // running max of (x.y - hy) per query
__device__ float g_hsum;         // sum of 2*hx over all queries (both dirs)

typedef unsigned long long u64;

__device__ __forceinline__ u64 fma2(u64 a, u64 b, u64 c) {
    u64 d;
    asm("fma.rn.f32x2 %0, %1, %2, %3;" : "=l"(d) : "l"(a), "l"(b), "l"(c));
    return d;
}
__device__ __forceinline__ u64 pack2(float x) {
    u64 d;
    asm("mov.b64 %0, {%1, %1};" : "=l"(d) : "f"(x));
    return d;
}
__device__ __forceinline__ void unpack2(u64 v, float& lo, float& hi) {
    asm("mov.b64 {%0, %1}, %2;" : "=f"(lo), "=f"(hi) : "l"(v));
}
__device__ __forceinline__ void lds_v2u64(unsigned addr, u64& a, u64& b) {
    asm volatile("ld.shared.v2.u64 {%0, %1}, [%2];" : "=l"(a), "=l"(b) : "r"(addr));
}
__device__ __forceinline__ void atomicMaxFloat(float* addr, float val) {
    if (val >= 0.0f) atomicMax((int*)addr, __float_as_int(val));
    else             atomicMin((unsigned*)addr, __float_as_uint(val));
}

__global__ void chamfer_init_kernel() {
    int i = blockIdx.x * blockDim.x + threadIdx.x;
    if (i < NQUERY) g_mx[i] = __int_as_float(0xff800000);  // -inf
    if (i == 0) g_hsum = 0.0f;
}

__global__ __launch_bounds__(THREADS)
void chamfer_main_kernel(const float* __restrict__ pred,
                         const float* __restrict__ targ) {
    const int u     = blockIdx.x;
    const int tc    = u & (NTC - 1);
    const int qt    = (u / NTC) & (NQT - 1);
    const int bd    = u / (NTC * NQT);
    const int b     = bd & (NBATCH - 1);
    const int dir   = bd >> 2;

    const float* __restrict__ X = dir ? targ : pred;
    const float* __restrict__ Y = dir ? pred : targ;
    const float* __restrict__ Xb = X + (size_t)b * 3 * NPTS;
    const float* __restrict__ Yb = Y + (size_t)b * 3 * NPTS;

    __shared__ float s_y0[TCHUNK], s_y1[TCHUNK], s_y2[TCHUNK], s_nh[TCHUNK];
    __shared__ float wsum[THREADS / 32];

    const int tid = threadIdx.x;

    // ---- stage target chunk into SoA smem: {y0, y1, y2, -0.5*||y||^2} ----
    const int tbase = tc * TCHUNK;
    #pragma unroll
    for (int i = tid; i < TCHUNK; i += THREADS) {
        float y0 = Yb[tbase + i];
        float y1 = Yb[NPTS + tbase + i];
        float y2 = Yb[2 * NPTS + tbase + i];
        s_y0[i] = y0;
        s_y1[i] = y1;
        s_y2[i] = y2;
        s_nh[i] = -0.5f * (y0 * y0 + y1 * y1 + y2 * y2);
    }

    // ---- query points (QPT per thread) in registers, packed broadcast ----
    const int qbase = qt * QTILE;
    u64 xp0[QPT], xp1[QPT], xp2[QPT];
    float hx[QPT];
    #pragma unroll
    for (int q = 0; q < QPT; q++) {
        int n = qbase + q * THREADS + tid;
        float x0 = Xb[n];
        float x1 = Xb[NPTS + n];
        float x2 = Xb[2 * NPTS + n];
        xp0[q] = pack2(x0);
        xp1[q] = pack2(x1);
        xp2[q] = pack2(x2);
        hx[q] = 0.5f * (x0 * x0 + x1 * x1 + x2 * x2);
    }
    __syncthreads();

    unsigned a0 = (unsigned)__cvta_generic_to_shared(s_y0);
    unsigned a1 = (unsigned)__cvta_generic_to_shared(s_y1);
    unsigned a2 = (unsigned)__cvta_generic_to_shared(s_y2);
    unsigned ah = (unsigned)__cvta_generic_to_shared(s_nh);

    float m0[QPT], m1[QPT];
    #pragma unroll
    for (int q = 0; q < QPT; q++) { m0[q] = -3.402823466e38f; m1[q] = m0[q]; }

    // ---- main loop: 4 targets per iteration, all uniform-address broadcast LDS ----
    #pragma unroll 2
    for (int j = 0; j < TCHUNK / 4; j++) {
        u64 A0, A1, B0, B1, C0, C1, H0, H1;
        unsigned off = j * 16;
        lds_v2u64(a0 + off, A0, A1);
        lds_v2u64(a1 + off, B0, B1);
        lds_v2u64(a2 + off, C0, C1);
        lds_v2u64(ah + off, H0, H1);

        #pragma unroll
        for (int q = 0; q < QPT; q++) {
            u64 t0 = fma2(xp0[q], A0, H0);
            u64 t1 = fma2(xp0[q], A1, H1);
            t0 = fma2(xp1[q], B0, t0);
            t1 = fma2(xp1[q], B1, t1);
            t0 = fma2(xp2[q], C0, t0);
            t1 = fma2(xp2[q], C1, t1);
            float l0, h0, l1, h1;
            unpack2(t0, l0, h0);
            unpack2(t1, l1, h1);
            m0[q] = fmaxf(m0[q], l0);
            m1[q] = fmaxf(m1[q], h0);
            m0[q] = fmaxf(m0[q], l1);
            m1[q] = fmaxf(m1[q], h1);
        }
    }

    // ---- fold partial max into global scratch ----
    const int gq0 = bd * NPTS + qbase + tid;
    #pragma unroll
    for (int q = 0; q < QPT; q++) {
        atomicMaxFloat(&g_mx[gq0 + q * THREADS], fmaxf(m0[q], m1[q]));
    }

    // ---- tchunk 0 contributes sum of 2*hx (each query counted once) ----
    if (tc == 0) {
        float s = 0.0f;
        #pragma unroll
        for (int q = 0; q < QPT; q++) s += 2.0f * hx[q];
        #pragma unroll
        for (int off = 16; off > 0; off >>= 1)
            s += __shfl_xor_sync(0xffffffffu, s, off);
        if ((tid & 31) == 0) wsum[tid >> 5] = s;
        __syncthreads();
        if (tid == 0) {
            float t = 0.0f;
            #pragma unroll
            for (int i = 0; i < THREADS / 32; i++) t += wsum[i];
            atomicAdd(&g_hsum, t);
        }
    }
}

__global__ __launch_bounds__(1024)
void chamfer_reduce_kernel(float* __restrict__ out) {
    __shared__ float wsum[32];
    float s = 0.0f;
    for (int i = threadIdx.x; i < NQUERY; i += 1024) s += g_mx[i];
    #pragma unroll
    for (int off = 16; off > 0; off >>= 1)
        s += __shfl_xor_sync(0xffffffffu, s, off);
    if ((threadIdx.x & 31) == 0) wsum[threadIdx.x >> 5] = s;
    __syncthreads();
    if (threadIdx.x == 0) {
        float t = 0.0f;
        #pragma unroll
        for (int i = 0; i < 32; i++) t += wsum[i];
        out[0] = (g_hsum - 2.0f * t) * (1.0f / (float)(NBATCH * NPTS));
    }
}

extern "C" void kernel_launch(void* const* d_in, const int* in_sizes, int n_in,
                              void* d_out, int out_size) {
    const float* pred = (const float*)d_in[0];
    const float* targ = (const float*)d_in[1];
    float* out = (float*)d_out;

    chamfer_init_kernel<<<NQUERY / 256, 256>>>();
    chamfer_main_kernel<<<NUNITS, THREADS>>>(pred, targ);
    chamfer_reduce_kernel<<<1, 1024>>>(out);
}

// round 16
// speedup vs baseline: 1.1770x; 1.0060x over previous
#include <cuda_runtime.h>
#include <cuda_bf16.h>

// ChamferDistance: B=4, C=3, N=M=8192, fp32.
// dist(n,m) = 2*hx - 2*(x.y - hy);  min_m dist = 2*hx - 2*max_m(x.y - hy)
// R16 = R15's main loop byte-for-byte; protocol change only:
//   - blocks plain-store partial (max - hx) into private slots (no atomics,
//     no init kernel: every slot written every replay)
//   - parallel 64-block reduce; last block finalizes and RESETS the counter
//     (statically-zero counter correct on every graph replay)

#define NPTS     8192
#define NBATCH   4
#define THREADS  128
#define QPT      4            // queries per thread -> 512 queries per block
#define QTILE    (THREADS * QPT)
#define TCHUNK   512          // targets per block
#define NQT      (NPTS / QTILE)    // 16 query tiles
#define NTC      (NPTS / TCHUNK)   // 16 target chunks
#define NUNITS   (2 * NBATCH * NQT * NTC)   // 2048
#define NQUERY   (2 * NBATCH * NPTS)        // 65536
#define RBLOCKS  64
#define RTHREADS 1024

__device__ float g_part[NTC * NQUERY];   // [tc][key] partial (max t' - hx)
__device__ float g_bsum[RBLOCKS];
__device__ unsigned g_count;             // zero-init; last reduce block resets it

typedef unsigned long long u64;

__device__ __forceinline__ u64 fma2(u64 a, u64 b, u64 c) {
    u64 d;
    asm("fma.rn.f32x2 %0, %1, %2, %3;" : "=l"(d) : "l"(a), "l"(b), "l"(c));
    return d;
}
__device__ __forceinline__ u64 pack2(float x) {
    u64 d;
    asm("mov.b64 %0, {%1, %1};" : "=l"(d) : "f"(x));
    return d;
}
__device__ __forceinline__ void unpack2(u64 v, float& lo, float& hi) {
    asm("mov.b64 {%0, %1}, %2;" : "=f"(lo), "=f"(hi) : "l"(v));
}
__device__ __forceinline__ void lds_v2u64(unsigned addr, u64& a, u64& b) {
    asm volatile("ld.shared.v2.u64 {%0, %1}, [%2];" : "=l"(a), "=l"(b) : "r"(addr));
}

__global__ __launch_bounds__(THREADS)
void chamfer_main_kernel(const float* __restrict__ pred,
                         const float* __restrict__ targ) {
    const int u     = blockIdx.x;
    const int tc    = u & (NTC - 1);
    const int qt    = (u / NTC) & (NQT - 1);
    const int bd    = u / (NTC * NQT);
    const int b     = bd & (NBATCH - 1);
    const int dir   = bd >> 2;

    const float* __restrict__ X = dir ? targ : pred;
    const float* __restrict__ Y = dir ? pred : targ;
    const float* __restrict__ Xb = X + (size_t)b * 3 * NPTS;
    const float* __restrict__ Yb = Y + (size_t)b * 3 * NPTS;

    __shared__ float s_y0[TCHUNK], s_y1[TCHUNK], s_y2[TCHUNK], s_nh[TCHUNK];

    const int tid = threadIdx.x;

    // ---- stage target chunk into SoA smem: {y0, y1, y2, -0.5*||y||^2} ----
    const int tbase = tc * TCHUNK;
    #pragma unroll
    for (int i = tid; i < TCHUNK; i += THREADS) {
        float y0 = Yb[tbase + i];
        float y1 = Yb[NPTS + tbase + i];
        float y2 = Yb[2 * NPTS + tbase + i];
        s_y0[i] = y0;
        s_y1[i] = y1;
        s_y2[i] = y2;
        s_nh[i] = -0.5f * (y0 * y0 + y1 * y1 + y2 * y2);
    }

    // ---- query points (QPT per thread) in registers, packed broadcast ----
    const int qbase = qt * QTILE;
    u64 xp0[QPT], xp1[QPT], xp2[QPT];
    float hx[QPT];
    #pragma unroll
    for (int q = 0; q < QPT; q++) {
        int n = qbase + q * THREADS + tid;
        float x0 = Xb[n];
        float x1 = Xb[NPTS + n];
        float x2 = Xb[2 * NPTS + n];
        xp0[q] = pack2(x0);
        xp1[q] = pack2(x1);
        xp2[q] = pack2(x2);
        hx[q] = 0.5f * (x0 * x0 + x1 * x1 + x2 * x2);
    }
    __syncthreads();

    unsigned a0 = (unsigned)__cvta_generic_to_shared(s_y0);
    unsigned a1 = (unsigned)__cvta_generic_to_shared(s_y1);
    unsigned a2 = (unsigned)__cvta_generic_to_shared(s_y2);
    unsigned ah = (unsigned)__cvta_generic_to_shared(s_nh);

    float m0[QPT], m1[QPT];
    #pragma unroll
    for (int q = 0; q < QPT; q++) { m0[q] = -3.402823466e38f; m1[q] = m0[q]; }

    // ---- main loop: 4 targets per iteration, all uniform-address broadcast LDS ----
    #pragma unroll 2
    for (int j = 0; j < TCHUNK / 4; j++) {
        u64 A0, A1, B0, B1, C0, C1, H0, H1;
        unsigned off = j * 16;
        lds_v2u64(a0 + off, A0, A1);
        lds_v2u64(a1 + off, B0, B1);
        lds_v2u64(a2 + off, C0, C1);
        lds_v2u64(ah + off, H0, H1);

        #pragma unroll
        for (int q = 0; q < QPT; q++) {
            u64 t0 = fma2(xp0[q], A0, H0);
            u64 t1 = fma2(xp0[q], A1, H1);
            t0 = fma2(xp1[q], B0, t0);
            t1 = fma2(xp1[q], B1, t1);
            t0 = fma2(xp2[q], C0, t0);
            t1 = fma2(xp2[q], C1, t1);
            float l0, h0, l1, h1;
            unpack2(t0, l0, h0);
            unpack2(t1, l1, h1);
            m0[q] = fmaxf(m0[q], l0);
            m1[q] = fmaxf(m1[q], h0);
            m0[q] = fmaxf(m0[q], l1);
            m1[q] = fmaxf(m1[q], h1);
        }
    }

    // ---- epilogue: plain-store private partial (max t' - hx); no atomics ----
    const int key0 = bd * NPTS + qbase + tid;
    float* __restrict__ dst = &g_part[(size_t)tc * NQUERY + key0];
    #pragma unroll
    for (int q = 0; q < QPT; q++)
        dst[q * THREADS] = fmaxf(m0[q], m1[q]) - hx[q];
}

__global__ __launch_bounds__(RTHREADS)
void chamfer_reduce_kernel(float* __restrict__ out) {
    __shared__ float wsum[RTHREADS / 32];
    const int tid = threadIdx.x;
    const int key = blockIdx.x * RTHREADS + tid;

    // fold the 16 tc-partials of this key -> t_full (coalesced loads)
    float v = g_part[key];
    #pragma unroll
    for (int t = 1; t < NTC; t++)
        v = fmaxf(v, g_part[(size_t)t * NQUERY + key]);

    // block sum
    #pragma unroll
    for (int off = 16; off > 0; off >>= 1)
        v += __shfl_xor_sync(0xffffffffu, v, off);
    if ((tid & 31) == 0) wsum[tid >> 5] = v;
    __syncthreads();
    if (tid == 0) {
        float s = 0.0f;
        #pragma unroll
        for (int i = 0; i < RTHREADS / 32; i++) s += wsum[i];
        g_bsum[blockIdx.x] = s;
        __threadfence();
        unsigned c = atomicAdd(&g_count, 1u);
        if (c == RBLOCKS - 1) {
            float tot = 0.0f;
            #pragma unroll
            for (int i = 0; i < RBLOCKS; i++) tot += __ldcg(&g_bsum[i]);
            // min dist per query = -2 * t_full; two means each over B*NPTS
            out[0] = tot * (-2.0f / (float)(NBATCH * NPTS));
            g_count = 0u;   // self-reset for the next graph replay
        }
    }
}

extern "C" void kernel_launch(void* const* d_in, const int* in_sizes, int n_in,
                              void* d_out, int out_size) {
    const float* pred = (const float*)d_in[0];
    const float* targ = (const float*)d_in[1];
    float* out = (float*)d_out;

    chamfer_main_kernel<<<NUNITS, THREADS>>>(pred, targ);
    chamfer_reduce_kernel<<<RBLOCKS, RTHREADS>>>(out);
}